// round 10
// baseline (speedup 1.0000x reference)
#include <cuda_runtime.h>
#include <cuda_fp16.h>
#include <math.h>
#include <stdint.h>

#define EPS_BN 1e-5f
#define NB 16
#define NC 256
#define CQ 64
#define GHID 128
#define GIN 320

// ---------------------------------------------------------------------------
// Scratch (allocation-free device globals)
// ---------------------------------------------------------------------------
__device__ __align__(16) uint32_t g_ef1h[NB*32*64*64];  // half2 [b][icpair32][h][w]
__device__ __align__(16) uint32_t g_ef2h[NB*32*64*64];  // half2 [b][ocpair32][h][w]
__device__ float g_xpool[NB*NC];    // raw sums (scaled in gate)
__device__ float g_epool[NB*CQ];    // raw sums
__device__ float g_gate[NB*NC];
__device__ __align__(16) uint32_t g_w1h[9*64*128];      // half2 [tap][oc][icpair]
__device__ __align__(16) uint32_t g_w2h[9*64*32];
__device__ __align__(16) uint32_t g_owh[256*32];        // half2 [oc][icpair]

__device__ __forceinline__ uint32_t packh2(float lo, float hi){
    __half2 h = __halves2half2(__float2half_rn(lo), __float2half_rn(hi));
    return *(uint32_t*)&h;
}

// m16n8k16 fp16 MMA, fp32 accum. A row-major, B col-major.
__device__ __forceinline__ void mma16(float* d, const uint32_t* a, const uint32_t* b){
    asm volatile("mma.sync.aligned.m16n8k16.row.col.f32.f16.f16.f32 "
        "{%0,%1,%2,%3}, {%4,%5,%6,%7}, {%8,%9}, {%0,%1,%2,%3};"
        : "+f"(d[0]), "+f"(d[1]), "+f"(d[2]), "+f"(d[3])
        : "r"(a[0]), "r"(a[1]), "r"(a[2]), "r"(a[3]), "r"(b[0]), "r"(b[1]));
}

// ---------------------------------------------------------------------------
// Weight transforms + pool zeroing.
// items: [0,73728) w1 | [,92160) w2 | [,100352) out_w | [,104448) zero xpool
//        | [,105472) zero epool
// ---------------------------------------------------------------------------
__global__ void wtrans_kernel(const float* __restrict__ w1, const float* __restrict__ w2,
                              const float* __restrict__ ow)
{
    int i = blockIdx.x * 256 + threadIdx.x;
    if (i < 9*64*128) {
        int tap = i / (64*128); int rem = i - tap*(64*128);
        int oc = rem >> 7, ip = rem & 127;
        g_w1h[i] = packh2(w1[(oc*256 + 2*ip)*9 + tap], w1[(oc*256 + 2*ip + 1)*9 + tap]);
        return;
    }
    int j = i - 9*64*128;
    if (j < 9*64*32) {
        int tap = j / (64*32); int rem = j - tap*(64*32);
        int oc = rem >> 5, ip = rem & 31;
        g_w2h[j] = packh2(w2[(oc*64 + 2*ip)*9 + tap], w2[(oc*64 + 2*ip + 1)*9 + tap]);
        return;
    }
    j -= 9*64*32;
    if (j < 256*32) {
        int oc = j >> 5, ip = j & 31;
        g_owh[j] = packh2(ow[oc*64 + 2*ip], ow[oc*64 + 2*ip + 1]);
        return;
    }
    j -= 256*32;
    if (j < NB*NC) { g_xpool[j] = 0.f; return; }
    j -= NB*NC;
    if (j < NB*CQ) { g_epool[j] = 0.f; return; }
}

// ---------------------------------------------------------------------------
// conv3x3 + BN + ReLU via mma.sync fp16 tap-split implicit GEMM.
// Block: 128 px (2 rows x 64 w) x 64 oc. 4 warps, warp tile 64px x 32oc.
// Grid: (32 rowpairs, 16 batches). Dynamic SMEM: 34304 B.
// CIN==256: reads x fp32 (fused x_pool), writes g_ef1h half2.
// CIN==64:  reads g_ef1h, writes g_ef2h half2 (fused e_pool).
// ---------------------------------------------------------------------------
template<int CIN>
__global__ __launch_bounds__(128)
void conv_mma(const float* __restrict__ xg,
              const float* __restrict__ cb,
              const float* __restrict__ bg, const float* __restrict__ bb,
              const float* __restrict__ bm, const float* __restrict__ bv)
{
    extern __shared__ uint32_t smu[];
    uint32_t* slab = smu;                         // 4224
    uint32_t* Bs   = smu + 4224;                  // 2x1280
    float* sinv    = (float*)(smu + 8448);        // 64
    float* sbeta   = (float*)(smu + 8512);        // 64

    const uint32_t* __restrict__ wth = (CIN == NC) ? (const uint32_t*)g_w1h : (const uint32_t*)g_w2h;
    const int IPC = CIN / 2;

    const int tid = threadIdx.x, lane = tid & 31, wid = tid >> 5;
    const int warpM = wid & 1, warpN = wid >> 1;     // M: 2x64px, N: 2x32oc
    const int r = lane >> 2, c = lane & 3;
    const int b = blockIdx.y, h0 = blockIdx.x * 2;

    if (tid < 64) {
        float inv = bg[tid] * rsqrtf(bv[tid] + EPS_BN);
        sinv[tid]  = inv;
        sbeta[tid] = (cb[tid] - bm[tid]) * inv + bb[tid];
    }
    // halo columns (ws=0, ws=65) always zero: 16 ip * 4 rs * 2
    if (tid < 128) {
        int ip = tid >> 3, rem = tid & 7, rs = rem >> 1, e = rem & 1;
        slab[ip*264 + rs*66 + e*65] = 0u;
    }

    float d[4][4][4];
    #pragma unroll
    for (int mt = 0; mt < 4; mt++)
        #pragma unroll
        for (int nt = 0; nt < 4; nt++)
            #pragma unroll
            for (int q = 0; q < 4; q++) d[mt][nt][q] = 0.f;

    const int CH = CIN / 32;
    for (int ch = 0; ch < CH; ch++) {
        __syncthreads();   // prior readers done with slab
        if (CIN == NC) {
            // pack x fp32 -> half2; fused x_pool over interior rows (rs 1,2)
            const float* xs = xg + ((size_t)(b*CIN + ch*32)) * 4096;
            #pragma unroll
            for (int k = 0; k < 8; k++) {
                int i = tid + k*128;
                int ip = i >> 6, rem = i & 63, rs = rem >> 4, q = rem & 15;
                int gr = h0 - 1 + rs;
                uint32_t v0 = 0, v1 = 0, v2 = 0, v3 = 0;
                float sa = 0.f, sb = 0.f;
                if ((unsigned)gr < 64u) {
                    const float* p0 = xs + (2*ip)*4096 + gr*64 + q*4;
                    float4 a4 = *(const float4*)p0;
                    float4 b4 = *(const float4*)(p0 + 4096);
                    v0 = packh2(a4.x, b4.x); v1 = packh2(a4.y, b4.y);
                    v2 = packh2(a4.z, b4.z); v3 = packh2(a4.w, b4.w);
                    if (rs == 1 || rs == 2) {
                        sa = (a4.x + a4.y) + (a4.z + a4.w);
                        sb = (b4.x + b4.y) + (b4.z + b4.w);
                    }
                }
                uint32_t* dst = slab + ip*264 + rs*66 + 1 + q*4;
                dst[0]=v0; dst[1]=v1; dst[2]=v2; dst[3]=v3;
                // warp reduce (ip is warp-uniform), 1 atomic per channel pair
                #pragma unroll
                for (int o = 16; o > 0; o >>= 1) {
                    sa += __shfl_down_sync(0xffffffffu, sa, o);
                    sb += __shfl_down_sync(0xffffffffu, sb, o);
                }
                if (lane == 0) {
                    atomicAdd(&g_xpool[b*NC + ch*32 + 2*ip],     sa);
                    atomicAdd(&g_xpool[b*NC + ch*32 + 2*ip + 1], sb);
                }
            }
        } else {
            // ef1 already half2-packed: raw uint4 copy
            const uint32_t* es = g_ef1h + ((size_t)(b*32 + ch*16)) * 4096;
            #pragma unroll
            for (int k = 0; k < 8; k++) {
                int i = tid + k*128;
                int ip = i >> 6, rem = i & 63, rs = rem >> 4, q = rem & 15;
                int gr = h0 - 1 + rs;
                uint4 v = make_uint4(0u,0u,0u,0u);
                if ((unsigned)gr < 64u)
                    v = *(const uint4*)(es + ip*4096 + gr*64 + q*4);
                uint32_t* dst = slab + ip*264 + rs*66 + 1 + q*4;
                dst[0]=v.x; dst[1]=v.y; dst[2]=v.z; dst[3]=v.w;
            }
        }

        for (int tap = 0; tap < 9; tap++) {
            const int buf = (ch*9 + tap) & 1;
            // stage B half2 [oc64][icpair16] pad 20 (double-buffered)
            {
                const uint32_t* ws_ = wth + ((size_t)tap*64)*IPC + ch*16;
                #pragma unroll
                for (int i = tid; i < 256; i += 128) {
                    int oc = i >> 2, iq = i & 3;
                    *(uint4*)(Bs + buf*1280 + oc*20 + iq*4) =
                        *(const uint4*)(ws_ + oc*IPC + iq*4);
                }
            }
            __syncthreads();
            const int kh = tap / 3, kw = tap - kh*3;
            const int rowoff = (warpM + kh)*66 + kw;
            const uint32_t* Bb = Bs + buf*1280;

            #pragma unroll
            for (int s = 0; s < 2; s++) {
                const int ip0 = s*8 + c;
                uint32_t a[4][4];
                #pragma unroll
                for (int mt = 0; mt < 4; mt++) {
                    int ws = rowoff + mt*16 + r;
                    a[mt][0] = slab[ip0*264 + ws];
                    a[mt][1] = slab[ip0*264 + ws + 8];
                    a[mt][2] = slab[(ip0+4)*264 + ws];
                    a[mt][3] = slab[(ip0+4)*264 + ws + 8];
                }
                uint32_t bf[4][2];
                #pragma unroll
                for (int nt = 0; nt < 4; nt++) {
                    int oc = warpN*32 + nt*8 + r;
                    bf[nt][0] = Bb[oc*20 + ip0];
                    bf[nt][1] = Bb[oc*20 + ip0 + 4];
                }
                #pragma unroll
                for (int mt = 0; mt < 4; mt++)
                    #pragma unroll
                    for (int nt = 0; nt < 4; nt++)
                        mma16(d[mt][nt], a[mt], bf[nt]);
            }
        }
    }

    // Epilogue: BN+ReLU -> sD fp32, then pool (conv2) + half2 pack + store
    __syncthreads();
    float* sD = (float*)smu;   // [oc64][px132] = 8448 fl (sinv/sbeta live above)
    #pragma unroll
    for (int mt = 0; mt < 4; mt++) {
        int px0 = warpM*64 + mt*16 + r;
        #pragma unroll
        for (int nt = 0; nt < 4; nt++) {
            int oc0 = warpN*32 + nt*8 + c*2;
            float i0 = sinv[oc0],   b0 = sbeta[oc0];
            float i1 = sinv[oc0+1], b1 = sbeta[oc0+1];
            float v0 = d[mt][nt][0]*i0 + b0;
            float v1 = d[mt][nt][1]*i1 + b1;
            float v2 = d[mt][nt][2]*i0 + b0;
            float v3 = d[mt][nt][3]*i1 + b1;
            sD[oc0*132 + px0]           = v0 > 0.f ? v0 : 0.f;
            sD[(oc0+1)*132 + px0]       = v1 > 0.f ? v1 : 0.f;
            sD[oc0*132 + px0 + 8]       = v2 > 0.f ? v2 : 0.f;
            sD[(oc0+1)*132 + px0 + 8]   = v3 > 0.f ? v3 : 0.f;
        }
    }
    __syncthreads();
    if (CIN == CQ) {
        // fused e_pool: exact fp32 sums from sD
        int oc = tid >> 1, hv = tid & 1;
        const float* row = sD + oc*132 + hv*64;
        float s = 0.f;
        #pragma unroll
        for (int k2 = 0; k2 < 64; k2++) s += row[k2];
        s += __shfl_xor_sync(0xffffffffu, s, 1);
        if (hv == 0) atomicAdd(&g_epool[b*CQ + oc], s);
    }
    // pack oc pairs -> half2 output
    uint32_t* outh = (CIN == NC) ? (uint32_t*)g_ef1h : (uint32_t*)g_ef2h;
    #pragma unroll
    for (int k = 0; k < 8; k++) {
        int i = tid + k*128;
        int op = i >> 5, pxq = i & 31;
        int px = pxq * 4, rs = px >> 6, w = px & 63;
        const float* r0 = sD + (2*op)*132 + px;
        const float* r1 = sD + (2*op+1)*132 + px;
        uint4 v;
        v.x = packh2(r0[0], r1[0]); v.y = packh2(r0[1], r1[1]);
        v.z = packh2(r0[2], r1[2]); v.w = packh2(r0[3], r1[3]);
        *(uint4*)(outh + ((size_t)(b*32 + op)*64 + h0 + rs)*64 + w) = v;
    }
}

// ---------------------------------------------------------------------------
// Output 1x1 GEMM + gated residual, fp16 MMA. Block 64px x 64oc, 4 warps.
// Grid: (64 h, 4 oc-chunks, 16 b). SMEM: 18944 B. A/B are raw half2 copies.
// ---------------------------------------------------------------------------
__global__ __launch_bounds__(128)
void out_mma(const float* __restrict__ x, const float* __restrict__ ob,
             float* __restrict__ out)
{
    extern __shared__ uint32_t smu[];
    uint32_t* sAh  = smu;            // 2304  [ip32][72]
    uint32_t* sBh  = smu + 2304;     // 2304  [oc64][36]
    float* sgate   = (float*)(smu + 4608);
    float* sob     = (float*)(smu + 4672);

    const int tid = threadIdx.x, lane = tid & 31, warpN = tid >> 5;
    const int r = lane >> 2, c = lane & 3;
    const int h = blockIdx.x, och = blockIdx.y, b = blockIdx.z;
    const int ocb = och * 64;

    if (tid < 64) {
        sgate[tid] = g_gate[b*256 + ocb + tid];
        sob[tid]   = ob[ocb + tid];
    }
    // A: raw copy from g_ef2h [ip32][w64]
    #pragma unroll
    for (int i = tid; i < 512; i += 128) {
        int ip = i >> 4, wq = i & 15;
        *(uint4*)(sAh + ip*72 + wq*4) =
            *(const uint4*)(g_ef2h + ((size_t)(b*32 + ip)*64 + h)*64 + wq*4);
    }
    // B: raw copy from g_owh [oc][ip32]
    #pragma unroll
    for (int i = tid; i < 512; i += 128) {
        int oc = i >> 3, q = i & 7;
        *(uint4*)(sBh + oc*36 + q*4) =
            *(const uint4*)(g_owh + (ocb + oc)*32 + q*4);
    }
    __syncthreads();

    float d[4][2][4];
    #pragma unroll
    for (int mt = 0; mt < 4; mt++)
        #pragma unroll
        for (int nt = 0; nt < 2; nt++)
            #pragma unroll
            for (int q = 0; q < 4; q++) d[mt][nt][q] = 0.f;

    #pragma unroll
    for (int s = 0; s < 4; s++) {
        const int ip0 = s*8 + c;
        uint32_t a[4][4];
        #pragma unroll
        for (int mt = 0; mt < 4; mt++) {
            int ws = mt*16 + r;
            a[mt][0] = sAh[ip0*72 + ws];
            a[mt][1] = sAh[ip0*72 + ws + 8];
            a[mt][2] = sAh[(ip0+4)*72 + ws];
            a[mt][3] = sAh[(ip0+4)*72 + ws + 8];
        }
        uint32_t bf[2][2];
        #pragma unroll
        for (int nt = 0; nt < 2; nt++) {
            int oc = warpN*16 + nt*8 + r;
            bf[nt][0] = sBh[oc*36 + ip0];
            bf[nt][1] = sBh[oc*36 + ip0 + 4];
        }
        #pragma unroll
        for (int mt = 0; mt < 4; mt++)
            #pragma unroll
            for (int nt = 0; nt < 2; nt++)
                mma16(d[mt][nt], a[mt], bf[nt]);
    }

    __syncthreads();
    float* sD = (float*)smu;   // [oc64][w68] = 4352 fl (sgate/sob live above)
    #pragma unroll
    for (int mt = 0; mt < 4; mt++) {
        int px0 = mt*16 + r;
        #pragma unroll
        for (int nt = 0; nt < 2; nt++) {
            int oc0 = warpN*16 + nt*8 + c*2;
            sD[oc0*68 + px0]         = d[mt][nt][0];
            sD[(oc0+1)*68 + px0]     = d[mt][nt][1];
            sD[oc0*68 + px0 + 8]     = d[mt][nt][2];
            sD[(oc0+1)*68 + px0 + 8] = d[mt][nt][3];
        }
    }
    __syncthreads();
    #pragma unroll
    for (int i = tid; i < 1024; i += 128) {
        int oc = i >> 4, wq = i & 15;
        size_t idx = (((size_t)b*256 + ocb + oc)*64 + h)*64 + wq*4;
        float4 xv = *(const float4*)(x + idx);
        float4 dv = *(const float4*)(sD + oc*68 + wq*4);
        float g = sgate[oc], o = sob[oc];
        float4 rv;
        rv.x = xv.x + g*(dv.x + o);
        rv.y = xv.y + g*(dv.y + o);
        rv.z = xv.z + g*(dv.z + o);
        rv.w = xv.w + g*(dv.w + o);
        *(float4*)(out + idx) = rv;
    }
}

// ---------------------------------------------------------------------------
// Gate MLP (pool sums scaled by 1/4096 here)
// ---------------------------------------------------------------------------
__global__ void gate_kernel(const float* __restrict__ g1w, const float* __restrict__ g1b,
                            const float* __restrict__ gg,  const float* __restrict__ gb2,
                            const float* __restrict__ gm,  const float* __restrict__ gv,
                            const float* __restrict__ g2w, const float* __restrict__ g2b)
{
    __shared__ float sg[GIN];
    __shared__ float sh[GHID];
    int b = blockIdx.x, tid = threadIdx.x;
    const float inv4096 = 1.f / 4096.f;
    for (int i = tid; i < NC; i += 128) sg[i] = g_xpool[b*NC + i] * inv4096;
    if (tid < CQ) sg[NC + tid] = g_epool[b*CQ + tid] * inv4096;
    __syncthreads();
    {
        int j = tid;
        float a = g1b[j];
        for (int k = 0; k < GIN; k++) a = fmaf(sg[k], g1w[j*GIN + k], a);
        float inv = gg[j] * rsqrtf(gv[j] + EPS_BN);
        a = (a - gm[j]) * inv + gb2[j];
        sh[j] = a > 0.f ? a : 0.f;
    }
    __syncthreads();
    for (int cc = tid; cc < NC; cc += 128) {
        float a = g2b[cc];
        for (int k = 0; k < GHID; k++) a = fmaf(sh[k], g2w[cc*GHID + k], a);
        g_gate[b*NC + cc] = 1.f / (1.f + expf(-a));
    }
}

// ---------------------------------------------------------------------------
extern "C" void kernel_launch(void* const* d_in, const int* in_sizes, int n_in,
                              void* d_out, int out_size)
{
    const float* x     = (const float*)d_in[0];
    const float* ec1_w = (const float*)d_in[1];
    const float* ec1_b = (const float*)d_in[2];
    const float* bn1_g = (const float*)d_in[3];
    const float* bn1_b = (const float*)d_in[4];
    const float* bn1_m = (const float*)d_in[5];
    const float* bn1_v = (const float*)d_in[6];
    const float* ec2_w = (const float*)d_in[7];
    const float* ec2_b = (const float*)d_in[8];
    const float* bn2_g = (const float*)d_in[9];
    const float* bn2_b = (const float*)d_in[10];
    const float* bn2_m = (const float*)d_in[11];
    const float* bn2_v = (const float*)d_in[12];
    const float* g1_w  = (const float*)d_in[13];
    const float* g1_b  = (const float*)d_in[14];
    const float* gbn_g = (const float*)d_in[15];
    const float* gbn_b = (const float*)d_in[16];
    const float* gbn_m = (const float*)d_in[17];
    const float* gbn_v = (const float*)d_in[18];
    const float* g2_w  = (const float*)d_in[19];
    const float* g2_b  = (const float*)d_in[20];
    const float* out_w = (const float*)d_in[21];
    const float* out_b = (const float*)d_in[22];
    float* out = (float*)d_out;

    const int CONV_SMEM = 34304;   // B (< 48KB)
    const int OUT_SMEM  = 18944;   // B (< 48KB)

    wtrans_kernel<<<412, 256>>>(ec1_w, ec2_w, out_w);

    conv_mma<NC><<<dim3(32, 16), 128, CONV_SMEM>>>(x, ec1_b, bn1_g, bn1_b, bn1_m, bn1_v);
    conv_mma<CQ><<<dim3(32, 16), 128, CONV_SMEM>>>(x, ec2_b, bn2_g, bn2_b, bn2_m, bn2_v);

    gate_kernel<<<NB, 128>>>(g1_w, g1_b, gbn_g, gbn_b, gbn_m, gbn_v, g2_w, g2_b);

    out_mma<<<dim3(64, 4, NB), 128, OUT_SMEM>>>(x, out_b, out);
}

// round 13
// speedup vs baseline: 1.6396x; 1.6396x over previous
#include <cuda_runtime.h>
#include <cuda_fp16.h>
#include <math.h>
#include <stdint.h>

#define EPS_BN 1e-5f
#define NB 16
#define NC 256
#define CQ 64
#define GHID 128
#define GIN 320

// ---------------------------------------------------------------------------
// Scratch (allocation-free device globals)
// ---------------------------------------------------------------------------
__device__ __align__(16) uint32_t g_ef1h[NB*32*64*64];  // half2 [b][icpair32][h][w]
__device__ __align__(16) uint32_t g_ef2h[NB*32*64*64];  // half2 [b][ocpair32][h][w]
__device__ float g_xpool[NB*NC];    // means
__device__ float g_epool[NB*CQ];    // means
__device__ float g_gate[NB*NC];
__device__ __align__(16) uint32_t g_w1h[9*64*128];      // half2 [tap][oc][icpair]
__device__ __align__(16) uint32_t g_w2h[9*64*32];
__device__ __align__(16) uint32_t g_owh[256*32];        // half2 [oc][icpair]

__device__ __forceinline__ uint32_t packh2(float lo, float hi){
    __half2 h = __halves2half2(__float2half_rn(lo), __float2half_rn(hi));
    return *(uint32_t*)&h;
}

// m16n8k16 fp16 MMA, fp32 accum. A row-major, B col-major.
__device__ __forceinline__ void mma16(float* d, const uint32_t* a, const uint32_t* b){
    asm volatile("mma.sync.aligned.m16n8k16.row.col.f32.f16.f16.f32 "
        "{%0,%1,%2,%3}, {%4,%5,%6,%7}, {%8,%9}, {%0,%1,%2,%3};"
        : "+f"(d[0]), "+f"(d[1]), "+f"(d[2]), "+f"(d[3])
        : "r"(a[0]), "r"(a[1]), "r"(a[2]), "r"(a[3]), "r"(b[0]), "r"(b[1]));
}

// ---------------------------------------------------------------------------
// Weight transforms: w1, w2 (tap-major) + out_w, all packed to half2
// items: [0,73728) w1 | [,92160) w2 | [,100352) out_w
// ---------------------------------------------------------------------------
__global__ void wtrans_kernel(const float* __restrict__ w1, const float* __restrict__ w2,
                              const float* __restrict__ ow)
{
    int i = blockIdx.x * 256 + threadIdx.x;
    if (i < 9*64*128) {
        int tap = i / (64*128); int rem = i - tap*(64*128);
        int oc = rem >> 7, ip = rem & 127;
        g_w1h[i] = packh2(w1[(oc*256 + 2*ip)*9 + tap], w1[(oc*256 + 2*ip + 1)*9 + tap]);
        return;
    }
    int j = i - 9*64*128;
    if (j < 9*64*32) {
        int tap = j / (64*32); int rem = j - tap*(64*32);
        int oc = rem >> 5, ip = rem & 31;
        g_w2h[j] = packh2(w2[(oc*64 + 2*ip)*9 + tap], w2[(oc*64 + 2*ip + 1)*9 + tap]);
        return;
    }
    j -= 9*64*32;
    if (j < 256*32) {
        int oc = j >> 5, ip = j & 31;
        g_owh[j] = packh2(ow[oc*64 + 2*ip], ow[oc*64 + 2*ip + 1]);
    }
}

// ---------------------------------------------------------------------------
// conv3x3 + BN + ReLU via mma.sync fp16 tap-split implicit GEMM.
// Block: 128 px (2 rows x 64 w) x 64 oc. 4 warps, warp tile 64px x 32oc.
// Grid: (32 rowpairs, 16 batches). Dynamic SMEM: 34304 B.
// CIN==256: reads x fp32, writes g_ef1h half2.
// CIN==64:  reads g_ef1h,  writes g_ef2h half2.
// ---------------------------------------------------------------------------
template<int CIN>
__global__ __launch_bounds__(128)
void conv_mma(const float* __restrict__ xg,
              const float* __restrict__ cb,
              const float* __restrict__ bg, const float* __restrict__ bb,
              const float* __restrict__ bm, const float* __restrict__ bv)
{
    extern __shared__ uint32_t smu[];
    uint32_t* slab = smu;                         // 4224
    uint32_t* Bs   = smu + 4224;                  // 2x1280
    float* sinv    = (float*)(smu + 8448);        // 64
    float* sbeta   = (float*)(smu + 8512);        // 64

    const uint32_t* __restrict__ wth = (CIN == NC) ? (const uint32_t*)g_w1h : (const uint32_t*)g_w2h;
    const int IPC = CIN / 2;

    const int tid = threadIdx.x, lane = tid & 31, wid = tid >> 5;
    const int warpM = wid & 1, warpN = wid >> 1;     // M: 2x64px, N: 2x32oc
    const int r = lane >> 2, c = lane & 3;
    const int b = blockIdx.y, h0 = blockIdx.x * 2;

    if (tid < 64) {
        float inv = bg[tid] * rsqrtf(bv[tid] + EPS_BN);
        sinv[tid]  = inv;
        sbeta[tid] = (cb[tid] - bm[tid]) * inv + bb[tid];
    }
    // halo columns (ws=0, ws=65) always zero: 16 ip * 4 rs * 2
    if (tid < 128) {
        int ip = tid >> 3, rem = tid & 7, rs = rem >> 1, e = rem & 1;
        slab[ip*264 + rs*66 + e*65] = 0u;
    }

    float d[4][4][4];
    #pragma unroll
    for (int mt = 0; mt < 4; mt++)
        #pragma unroll
        for (int nt = 0; nt < 4; nt++)
            #pragma unroll
            for (int q = 0; q < 4; q++) d[mt][nt][q] = 0.f;

    const int CH = CIN / 32;
    for (int ch = 0; ch < CH; ch++) {
        __syncthreads();   // prior readers done with slab
        if (CIN == NC) {
            // pack x fp32 -> half2 pairs
            const float* xs = xg + ((size_t)(b*CIN + ch*32)) * 4096;
            #pragma unroll
            for (int k = 0; k < 8; k++) {
                int i = tid + k*128;
                int ip = i >> 6, rem = i & 63, rs = rem >> 4, q = rem & 15;
                int gr = h0 - 1 + rs;
                uint32_t v0 = 0, v1 = 0, v2 = 0, v3 = 0;
                if ((unsigned)gr < 64u) {
                    const float* p0 = xs + (2*ip)*4096 + gr*64 + q*4;
                    float4 a4 = *(const float4*)p0;
                    float4 b4 = *(const float4*)(p0 + 4096);
                    v0 = packh2(a4.x, b4.x); v1 = packh2(a4.y, b4.y);
                    v2 = packh2(a4.z, b4.z); v3 = packh2(a4.w, b4.w);
                }
                uint32_t* dst = slab + ip*264 + rs*66 + 1 + q*4;
                dst[0]=v0; dst[1]=v1; dst[2]=v2; dst[3]=v3;
            }
        } else {
            // ef1 already half2-packed: raw uint4 copy
            const uint32_t* es = g_ef1h + ((size_t)(b*32 + ch*16)) * 4096;
            #pragma unroll
            for (int k = 0; k < 8; k++) {
                int i = tid + k*128;
                int ip = i >> 6, rem = i & 63, rs = rem >> 4, q = rem & 15;
                int gr = h0 - 1 + rs;
                uint4 v = make_uint4(0u,0u,0u,0u);
                if ((unsigned)gr < 64u)
                    v = *(const uint4*)(es + ip*4096 + gr*64 + q*4);
                uint32_t* dst = slab + ip*264 + rs*66 + 1 + q*4;
                dst[0]=v.x; dst[1]=v.y; dst[2]=v.z; dst[3]=v.w;
            }
        }

        for (int tap = 0; tap < 9; tap++) {
            const int buf = (ch*9 + tap) & 1;
            // stage B half2 [oc64][icpair16] pad 20 (double-buffered)
            {
                const uint32_t* ws_ = wth + ((size_t)tap*64)*IPC + ch*16;
                #pragma unroll
                for (int i = tid; i < 256; i += 128) {
                    int oc = i >> 2, iq = i & 3;
                    *(uint4*)(Bs + buf*1280 + oc*20 + iq*4) =
                        *(const uint4*)(ws_ + oc*IPC + iq*4);
                }
            }
            __syncthreads();
            const int kh = tap / 3, kw = tap - kh*3;
            const int rowoff = (warpM + kh)*66 + kw;
            const uint32_t* Bb = Bs + buf*1280;

            #pragma unroll
            for (int s = 0; s < 2; s++) {
                const int ip0 = s*8 + c;
                uint32_t a[4][4];
                #pragma unroll
                for (int mt = 0; mt < 4; mt++) {
                    int ws = rowoff + mt*16 + r;
                    a[mt][0] = slab[ip0*264 + ws];
                    a[mt][1] = slab[ip0*264 + ws + 8];
                    a[mt][2] = slab[(ip0+4)*264 + ws];
                    a[mt][3] = slab[(ip0+4)*264 + ws + 8];
                }
                uint32_t bf[4][2];
                #pragma unroll
                for (int nt = 0; nt < 4; nt++) {
                    int oc = warpN*32 + nt*8 + r;
                    bf[nt][0] = Bb[oc*20 + ip0];
                    bf[nt][1] = Bb[oc*20 + ip0 + 4];
                }
                #pragma unroll
                for (int mt = 0; mt < 4; mt++)
                    #pragma unroll
                    for (int nt = 0; nt < 4; nt++)
                        mma16(d[mt][nt], a[mt], bf[nt]);
            }
        }
    }

    // Epilogue: BN+ReLU -> sD fp32 -> half2 pack -> store
    __syncthreads();
    float* sD = (float*)smu;   // [oc64][px132] = 8448 fl (sinv/sbeta live above)
    #pragma unroll
    for (int mt = 0; mt < 4; mt++) {
        int px0 = warpM*64 + mt*16 + r;
        #pragma unroll
        for (int nt = 0; nt < 4; nt++) {
            int oc0 = warpN*32 + nt*8 + c*2;
            float i0 = sinv[oc0],   b0 = sbeta[oc0];
            float i1 = sinv[oc0+1], b1 = sbeta[oc0+1];
            float v0 = d[mt][nt][0]*i0 + b0;
            float v1 = d[mt][nt][1]*i1 + b1;
            float v2 = d[mt][nt][2]*i0 + b0;
            float v3 = d[mt][nt][3]*i1 + b1;
            sD[oc0*132 + px0]           = v0 > 0.f ? v0 : 0.f;
            sD[(oc0+1)*132 + px0]       = v1 > 0.f ? v1 : 0.f;
            sD[oc0*132 + px0 + 8]       = v2 > 0.f ? v2 : 0.f;
            sD[(oc0+1)*132 + px0 + 8]   = v3 > 0.f ? v3 : 0.f;
        }
    }
    __syncthreads();
    uint32_t* outh = (CIN == NC) ? (uint32_t*)g_ef1h : (uint32_t*)g_ef2h;
    #pragma unroll
    for (int k = 0; k < 8; k++) {
        int i = tid + k*128;
        int op = i >> 5, pxq = i & 31;
        int px = pxq * 4, rs = px >> 6, w = px & 63;
        const float* r0 = sD + (2*op)*132 + px;
        const float* r1 = sD + (2*op+1)*132 + px;
        uint4 v;
        v.x = packh2(r0[0], r1[0]); v.y = packh2(r0[1], r1[1]);
        v.z = packh2(r0[2], r1[2]); v.w = packh2(r0[3], r1[3]);
        *(uint4*)(outh + ((size_t)(b*32 + op)*64 + h0 + rs)*64 + w) = v;
    }
}

// ---------------------------------------------------------------------------
// Output 1x1 GEMM + gated residual, fp16 MMA. Block 64px x 64oc, 4 warps.
// Grid: (64 h, 4 oc-chunks, 16 b). SMEM: 18944 B. A/B are raw half2 copies.
// ---------------------------------------------------------------------------
__global__ __launch_bounds__(128)
void out_mma(const float* __restrict__ x, const float* __restrict__ ob,
             float* __restrict__ out)
{
    extern __shared__ uint32_t smu[];
    uint32_t* sAh  = smu;            // 2304  [ip32][72]
    uint32_t* sBh  = smu + 2304;     // 2304  [oc64][36]
    float* sgate   = (float*)(smu + 4608);
    float* sob     = (float*)(smu + 4672);

    const int tid = threadIdx.x, lane = tid & 31, warpN = tid >> 5;
    const int r = lane >> 2, c = lane & 3;
    const int h = blockIdx.x, och = blockIdx.y, b = blockIdx.z;
    const int ocb = och * 64;

    if (tid < 64) {
        sgate[tid] = g_gate[b*256 + ocb + tid];
        sob[tid]   = ob[ocb + tid];
    }
    // A: raw copy from g_ef2h [ip32][w64]
    #pragma unroll
    for (int i = tid; i < 512; i += 128) {
        int ip = i >> 4, wq = i & 15;
        *(uint4*)(sAh + ip*72 + wq*4) =
            *(const uint4*)(g_ef2h + ((size_t)(b*32 + ip)*64 + h)*64 + wq*4);
    }
    // B: raw copy from g_owh [oc][ip32]
    #pragma unroll
    for (int i = tid; i < 512; i += 128) {
        int oc = i >> 3, q = i & 7;
        *(uint4*)(sBh + oc*36 + q*4) =
            *(const uint4*)(g_owh + (ocb + oc)*32 + q*4);
    }
    __syncthreads();

    float d[4][2][4];
    #pragma unroll
    for (int mt = 0; mt < 4; mt++)
        #pragma unroll
        for (int nt = 0; nt < 2; nt++)
            #pragma unroll
            for (int q = 0; q < 4; q++) d[mt][nt][q] = 0.f;

    #pragma unroll
    for (int s = 0; s < 4; s++) {
        const int ip0 = s*8 + c;
        uint32_t a[4][4];
        #pragma unroll
        for (int mt = 0; mt < 4; mt++) {
            int ws = mt*16 + r;
            a[mt][0] = sAh[ip0*72 + ws];
            a[mt][1] = sAh[ip0*72 + ws + 8];
            a[mt][2] = sAh[(ip0+4)*72 + ws];
            a[mt][3] = sAh[(ip0+4)*72 + ws + 8];
        }
        uint32_t bf[2][2];
        #pragma unroll
        for (int nt = 0; nt < 2; nt++) {
            int oc = warpN*16 + nt*8 + r;
            bf[nt][0] = sBh[oc*36 + ip0];
            bf[nt][1] = sBh[oc*36 + ip0 + 4];
        }
        #pragma unroll
        for (int mt = 0; mt < 4; mt++)
            #pragma unroll
            for (int nt = 0; nt < 2; nt++)
                mma16(d[mt][nt], a[mt], bf[nt]);
    }

    __syncthreads();
    float* sD = (float*)smu;   // [oc64][w68] = 4352 fl (sgate/sob live above)
    #pragma unroll
    for (int mt = 0; mt < 4; mt++) {
        int px0 = mt*16 + r;
        #pragma unroll
        for (int nt = 0; nt < 2; nt++) {
            int oc0 = warpN*16 + nt*8 + c*2;
            sD[oc0*68 + px0]         = d[mt][nt][0];
            sD[(oc0+1)*68 + px0]     = d[mt][nt][1];
            sD[oc0*68 + px0 + 8]     = d[mt][nt][2];
            sD[(oc0+1)*68 + px0 + 8] = d[mt][nt][3];
        }
    }
    __syncthreads();
    #pragma unroll
    for (int i = tid; i < 1024; i += 128) {
        int oc = i >> 4, wq = i & 15;
        size_t idx = (((size_t)b*256 + ocb + oc)*64 + h)*64 + wq*4;
        float4 xv = *(const float4*)(x + idx);
        float4 dv = *(const float4*)(sD + oc*68 + wq*4);
        float g = sgate[oc], o = sob[oc];
        float4 rv;
        rv.x = xv.x + g*(dv.x + o);
        rv.y = xv.y + g*(dv.y + o);
        rv.z = xv.z + g*(dv.z + o);
        rv.w = xv.w + g*(dv.w + o);
        *(float4*)(out + idx) = rv;
    }
}

// ---------------------------------------------------------------------------
// pool_x: per-(b,c) mean of x (fp32). Grid NB*NC, 256 threads.
// ---------------------------------------------------------------------------
__global__ __launch_bounds__(256)
void pool_x_kernel(const float* __restrict__ xext)
{
    int bc = blockIdx.x, tid = threadIdx.x;
    const float4* p = (const float4*)(xext + (size_t)bc * 4096);
    float4 acc[4];
    #pragma unroll
    for (int j = 0; j < 4; j++) acc[j] = p[tid + j*256];
    float s = 0.f;
    #pragma unroll
    for (int j = 0; j < 4; j++) s += (acc[j].x + acc[j].y) + (acc[j].z + acc[j].w);
    __shared__ float red[8];
    #pragma unroll
    for (int o = 16; o > 0; o >>= 1) s += __shfl_down_sync(0xffffffffu, s, o);
    if ((tid & 31) == 0) red[tid >> 5] = s;
    __syncthreads();
    if (tid == 0) {
        float t = 0.f;
        #pragma unroll
        for (int i = 0; i < 8; i++) t += red[i];
        g_xpool[bc] = t * (1.f / 4096.f);
    }
}

// ---------------------------------------------------------------------------
// pool_e: per-(b,ocpair) means of g_ef2h (half2). Grid NB*32, 256 threads.
// ---------------------------------------------------------------------------
__global__ __launch_bounds__(256)
void pool_e_kernel()
{
    int bip = blockIdx.x, tid = threadIdx.x;
    int b = bip >> 5, ip = bip & 31;
    const uint4* p = (const uint4*)(g_ef2h + (size_t)bip * 4096);
    float slo = 0.f, shi = 0.f;
    #pragma unroll
    for (int j = 0; j < 4; j++) {
        uint4 v = p[tid + j*256];
        float2 f0 = __half22float2(*(__half2*)&v.x);
        float2 f1 = __half22float2(*(__half2*)&v.y);
        float2 f2 = __half22float2(*(__half2*)&v.z);
        float2 f3 = __half22float2(*(__half2*)&v.w);
        slo += (f0.x + f1.x) + (f2.x + f3.x);
        shi += (f0.y + f1.y) + (f2.y + f3.y);
    }
    __shared__ float redl[8], redh[8];
    #pragma unroll
    for (int o = 16; o > 0; o >>= 1) {
        slo += __shfl_down_sync(0xffffffffu, slo, o);
        shi += __shfl_down_sync(0xffffffffu, shi, o);
    }
    if ((tid & 31) == 0) { redl[tid >> 5] = slo; redh[tid >> 5] = shi; }
    __syncthreads();
    if (tid == 0) {
        float tl = 0.f, th = 0.f;
        #pragma unroll
        for (int i = 0; i < 8; i++) { tl += redl[i]; th += redh[i]; }
        g_epool[b*CQ + 2*ip]     = tl * (1.f / 4096.f);
        g_epool[b*CQ + 2*ip + 1] = th * (1.f / 4096.f);
    }
}

// ---------------------------------------------------------------------------
// Gate MLP: warp-parallel dot products. One block/sample, 256 threads (8 warps).
// ---------------------------------------------------------------------------
__global__ __launch_bounds__(256)
void gate_kernel(const float* __restrict__ g1w, const float* __restrict__ g1b,
                 const float* __restrict__ gg,  const float* __restrict__ gb2,
                 const float* __restrict__ gm,  const float* __restrict__ gv,
                 const float* __restrict__ g2w, const float* __restrict__ g2b)
{
    __shared__ float sg[GIN];
    __shared__ float sh[GHID];
    int b = blockIdx.x, tid = threadIdx.x;
    int lane = tid & 31, wid = tid >> 5;
    // FIX (R12 bug): strided loop covers all GIN=320 entries with 256 threads
    for (int i = tid; i < GIN; i += 256)
        sg[i] = (i < NC) ? g_xpool[b*NC + i] : g_epool[b*CQ + (i - NC)];
    __syncthreads();

    // Phase 1: h = relu(BN(g @ g1w^T + g1b)); 8 warps x 16 outputs
    #pragma unroll
    for (int jj = 0; jj < 16; jj++) {
        int j = wid*16 + jj;
        const float* wrow = g1w + j*GIN;
        float a = 0.f;
        #pragma unroll
        for (int k = lane; k < GIN; k += 32) a += sg[k] * wrow[k];
        #pragma unroll
        for (int o = 16; o > 0; o >>= 1) a += __shfl_down_sync(0xffffffffu, a, o);
        if (lane == 0) {
            a += g1b[j];
            float inv = gg[j] * rsqrtf(gv[j] + EPS_BN);
            a = (a - gm[j]) * inv + gb2[j];
            sh[j] = a > 0.f ? a : 0.f;
        }
    }
    __syncthreads();

    // Phase 2: gate = sigmoid(h @ g2w^T + g2b); 8 warps x 32 outputs
    #pragma unroll
    for (int jj = 0; jj < 32; jj++) {
        int cc = wid*32 + jj;
        const float* wrow = g2w + cc*GHID;
        float a = 0.f;
        #pragma unroll
        for (int k = lane; k < GHID; k += 32) a += sh[k] * wrow[k];
        #pragma unroll
        for (int o = 16; o > 0; o >>= 1) a += __shfl_down_sync(0xffffffffu, a, o);
        if (lane == 0)
            g_gate[b*NC + cc] = 1.f / (1.f + expf(-(a + g2b[cc])));
    }
}

// ---------------------------------------------------------------------------
extern "C" void kernel_launch(void* const* d_in, const int* in_sizes, int n_in,
                              void* d_out, int out_size)
{
    const float* x     = (const float*)d_in[0];
    const float* ec1_w = (const float*)d_in[1];
    const float* ec1_b = (const float*)d_in[2];
    const float* bn1_g = (const float*)d_in[3];
    const float* bn1_b = (const float*)d_in[4];
    const float* bn1_m = (const float*)d_in[5];
    const float* bn1_v = (const float*)d_in[6];
    const float* ec2_w = (const float*)d_in[7];
    const float* ec2_b = (const float*)d_in[8];
    const float* bn2_g = (const float*)d_in[9];
    const float* bn2_b = (const float*)d_in[10];
    const float* bn2_m = (const float*)d_in[11];
    const float* bn2_v = (const float*)d_in[12];
    const float* g1_w  = (const float*)d_in[13];
    const float* g1_b  = (const float*)d_in[14];
    const float* gbn_g = (const float*)d_in[15];
    const float* gbn_b = (const float*)d_in[16];
    const float* gbn_m = (const float*)d_in[17];
    const float* gbn_v = (const float*)d_in[18];
    const float* g2_w  = (const float*)d_in[19];
    const float* g2_b  = (const float*)d_in[20];
    const float* out_w = (const float*)d_in[21];
    const float* out_b = (const float*)d_in[22];
    float* out = (float*)d_out;

    const int CONV_SMEM = 34304;   // B (< 48KB)
    const int OUT_SMEM  = 18944;   // B (< 48KB)

    wtrans_kernel<<<392, 256>>>(ec1_w, ec2_w, out_w);

    conv_mma<NC><<<dim3(32, 16), 128, CONV_SMEM>>>(x, ec1_b, bn1_g, bn1_b, bn1_m, bn1_v);
    conv_mma<CQ><<<dim3(32, 16), 128, CONV_SMEM>>>(x, ec2_b, bn2_g, bn2_b, bn2_m, bn2_v);

    pool_x_kernel<<<NB*NC, 256>>>(x);
    pool_e_kernel<<<NB*32, 256>>>();

    gate_kernel<<<NB, 256>>>(g1_w, g1_b, gbn_g, gbn_b, gbn_m, gbn_v, g2_w, g2_b);

    out_mma<<<dim3(64, 4, NB), 128, OUT_SMEM>>>(x, out_b, out);
}